// round 2
// baseline (speedup 1.0000x reference)
#include <cuda_runtime.h>
#include <cstdint>

#define N_NODES 100000
#define N_EDGES 300000
#define HID 256

// ---------------- scratch (no runtime allocation allowed) ----------------
__device__ float g_H[(size_t)N_NODES * HID];    // projected / layer-1 features
__device__ float g_AGG[(size_t)N_NODES * HID];  // aggregation accumulator
__device__ float g_deg_out[N_NODES];
__device__ float g_deg_in[N_NODES];
__device__ float g_norm_out[N_NODES];
__device__ float g_norm_in[N_NODES];

// ---------------- small kernels ----------------
__global__ void zero_kernel() {
    int i = blockIdx.x * blockDim.x + threadIdx.x;
    const int total4 = N_NODES * HID / 4;
    if (i < total4) reinterpret_cast<float4*>(g_AGG)[i] = make_float4(0.f, 0.f, 0.f, 0.f);
    if (i < N_NODES) { g_deg_out[i] = 0.f; g_deg_in[i] = 0.f; }
}

__global__ void degree_kernel(const int* __restrict__ src,
                              const int* __restrict__ dst) {
    int e = blockIdx.x * blockDim.x + threadIdx.x;
    if (e < N_EDGES) {
        atomicAdd(&g_deg_out[src[e]], 1.f);
        atomicAdd(&g_deg_in[dst[e]], 1.f);
    }
}

__global__ void norm_kernel() {
    int i = blockIdx.x * blockDim.x + threadIdx.x;
    if (i < N_NODES) {
        g_norm_out[i] = rsqrtf(fmaxf(g_deg_out[i], 1.f));
        g_norm_in[i]  = rsqrtf(fmaxf(g_deg_in[i], 1.f));
    }
}

// ---------------- SGEMM: C[M,256] = (rowscale? diag(norm_in):I) * A[M,K] @ B (+bias, relu) ----
// BT=true : B stored [256, K]   (torch Linear: x @ W.T)
// BT=false: B stored [K, 256]   (DGL GraphConv: x @ W)
template<bool BT, bool SCALE_A, bool RELU>
__global__ void __launch_bounds__(256)
gemm_kernel(const float* __restrict__ A, const float* __restrict__ B,
            const float* __restrict__ bias, float* __restrict__ C,
            int M, int K) {
    constexpr int BM = 128, BN = 128, BK = 8;
    __shared__ float As[BK][BM + 4];
    __shared__ float Bs[BK][BN + 4];

    const int tid = threadIdx.x;           // 256 threads
    const int bm = blockIdx.y * BM;
    const int bn = blockIdx.x * BN;        // blockIdx.x in {0,1}
    const int ty = tid >> 4;               // 0..15 (row group)
    const int tx = tid & 15;               // 0..15 (col group)

    const int arow = tid >> 1;             // 0..127
    const int acol = (tid & 1) * 4;        // 0 or 4

    float acc[8][8];
#pragma unroll
    for (int i = 0; i < 8; i++)
#pragma unroll
        for (int j = 0; j < 8; j++) acc[i][j] = 0.f;

    for (int k0 = 0; k0 < K; k0 += BK) {
        // load A tile (128 x 8), K-contiguous, store transposed
        {
            float4 av = make_float4(0.f, 0.f, 0.f, 0.f);
            int gr = bm + arow;
            if (gr < M) av = *reinterpret_cast<const float4*>(A + (size_t)gr * K + (k0 + acol));
            As[acol + 0][arow] = av.x;
            As[acol + 1][arow] = av.y;
            As[acol + 2][arow] = av.z;
            As[acol + 3][arow] = av.w;
        }
        // load B tile
        if (BT) {
            // B is [256, K]; row index = output column n (always < 256, no guard needed)
            int gn = bn + arow;
            float4 bv = *reinterpret_cast<const float4*>(B + (size_t)gn * K + (k0 + acol));
            Bs[acol + 0][arow] = bv.x;
            Bs[acol + 1][arow] = bv.y;
            Bs[acol + 2][arow] = bv.z;
            Bs[acol + 3][arow] = bv.w;
        } else {
            // B is [K, 256]; tile 8 x 128, N-contiguous
            int gk = k0 + (tid >> 5);          // 0..7
            int gn = bn + (tid & 31) * 4;      // 0..124
            float4 bv = *reinterpret_cast<const float4*>(B + (size_t)gk * HID + gn);
            *reinterpret_cast<float4*>(&Bs[tid >> 5][(tid & 31) * 4]) = bv;
        }
        __syncthreads();

#pragma unroll
        for (int kk = 0; kk < BK; kk++) {
            float ar[8], br[8];
            *reinterpret_cast<float4*>(&ar[0]) = *reinterpret_cast<const float4*>(&As[kk][ty * 8]);
            *reinterpret_cast<float4*>(&ar[4]) = *reinterpret_cast<const float4*>(&As[kk][ty * 8 + 4]);
            *reinterpret_cast<float4*>(&br[0]) = *reinterpret_cast<const float4*>(&Bs[kk][tx * 8]);
            *reinterpret_cast<float4*>(&br[4]) = *reinterpret_cast<const float4*>(&Bs[kk][tx * 8 + 4]);
#pragma unroll
            for (int i = 0; i < 8; i++)
#pragma unroll
                for (int j = 0; j < 8; j++) acc[i][j] += ar[i] * br[j];
        }
        __syncthreads();
    }

    // epilogue: per-row scale, bias, relu, store float4x2 per row
    const int cbase = bn + tx * 8;
    float4 b0 = *reinterpret_cast<const float4*>(bias + cbase);
    float4 b1 = *reinterpret_cast<const float4*>(bias + cbase + 4);
#pragma unroll
    for (int i = 0; i < 8; i++) {
        int row = bm + ty * 8 + i;
        if (row < M) {
            float s = SCALE_A ? g_norm_in[row] : 1.f;
            float4 o0, o1;
            o0.x = acc[i][0] * s + b0.x;  o0.y = acc[i][1] * s + b0.y;
            o0.z = acc[i][2] * s + b0.z;  o0.w = acc[i][3] * s + b0.w;
            o1.x = acc[i][4] * s + b1.x;  o1.y = acc[i][5] * s + b1.y;
            o1.z = acc[i][6] * s + b1.z;  o1.w = acc[i][7] * s + b1.w;
            if (RELU) {
                o0.x = fmaxf(o0.x, 0.f); o0.y = fmaxf(o0.y, 0.f);
                o0.z = fmaxf(o0.z, 0.f); o0.w = fmaxf(o0.w, 0.f);
                o1.x = fmaxf(o1.x, 0.f); o1.y = fmaxf(o1.y, 0.f);
                o1.z = fmaxf(o1.z, 0.f); o1.w = fmaxf(o1.w, 0.f);
            }
            float* cp = C + (size_t)row * HID + cbase;
            *reinterpret_cast<float4*>(cp)     = o0;
            *reinterpret_cast<float4*>(cp + 4) = o1;
        }
    }
}

// ---------------- SpMM: AGG[dst] += H[src] * norm_out[src] ----------------
// 64 threads per edge, float4 gathers, 4 REDG adds per thread.
__global__ void spmm_kernel(const float* __restrict__ X,
                            const int* __restrict__ src,
                            const int* __restrict__ dst) {
    int idx = blockIdx.x * blockDim.x + threadIdx.x;
    int e = idx >> 6;
    if (e >= N_EDGES) return;
    int lane = idx & 63;
    int s = src[e];
    int d = dst[e];
    float w = g_norm_out[s];
    float4 v = *reinterpret_cast<const float4*>(X + (size_t)s * HID + lane * 4);
    float* o = g_AGG + (size_t)d * HID + lane * 4;
    atomicAdd(o + 0, v.x * w);
    atomicAdd(o + 1, v.y * w);
    atomicAdd(o + 2, v.z * w);
    atomicAdd(o + 3, v.w * w);
}

// ---------------- layer-1 epilogue: H = relu(AGG*norm_in + b1); AGG = 0 ----------------
__global__ void post1_kernel(const float* __restrict__ gc1_bias) {
    int i4 = blockIdx.x * blockDim.x + threadIdx.x;
    const int total4 = N_NODES * HID / 4;
    if (i4 >= total4) return;
    int row = i4 >> 6;               // 64 float4 per row
    int cb = (i4 & 63) * 4;
    float ni = g_norm_in[row];
    float4 a = reinterpret_cast<const float4*>(g_AGG)[i4];
    float4 b = *reinterpret_cast<const float4*>(gc1_bias + cb);
    float4 o;
    o.x = fmaxf(a.x * ni + b.x, 0.f);
    o.y = fmaxf(a.y * ni + b.y, 0.f);
    o.z = fmaxf(a.z * ni + b.z, 0.f);
    o.w = fmaxf(a.w * ni + b.w, 0.f);
    reinterpret_cast<float4*>(g_H)[i4] = o;
    reinterpret_cast<float4*>(g_AGG)[i4] = make_float4(0.f, 0.f, 0.f, 0.f);
}

// ---------------- tail: append semantic_weight (5 floats) ----------------
__global__ void tail_kernel(const float* __restrict__ sw, float* __restrict__ out, int off) {
    if (threadIdx.x < 5) out[off + threadIdx.x] = sw[threadIdx.x];
}

// ---------------- launch ----------------
extern "C" void kernel_launch(void* const* d_in, const int* in_sizes, int n_in,
                              void* d_out, int out_size) {
    const float* feat0 = (const float*)d_in[0];
    const float* feat1 = (const float*)d_in[1];
    const float* feat2 = (const float*)d_in[2];
    const float* fc_w0 = (const float*)d_in[3];
    const float* fc_b0 = (const float*)d_in[4];
    const float* fc_w1 = (const float*)d_in[5];
    const float* fc_b1 = (const float*)d_in[6];
    const float* fc_w2 = (const float*)d_in[7];
    const float* fc_b2 = (const float*)d_in[8];
    const float* gc1_bias = (const float*)d_in[9];
    const float* gc2_weight = (const float*)d_in[10];
    const float* gc2_bias = (const float*)d_in[11];
    const float* semantic_weight = (const float*)d_in[12];
    // JAX default x64-disabled: int64 in the reference is materialized as int32
    const int* src = (const int*)d_in[13];
    const int* dst = (const int*)d_in[14];
    float* out = (float*)d_out;

    float *H = nullptr, *AGG = nullptr;
    cudaGetSymbolAddress((void**)&H, g_H);
    cudaGetSymbolAddress((void**)&AGG, g_AGG);

    // 1. zero AGG + degree counters
    {
        int total4 = N_NODES * HID / 4;
        zero_kernel<<<(total4 + 255) / 256, 256>>>();
    }
    // 2. degrees
    degree_kernel<<<(N_EDGES + 255) / 256, 256>>>(src, dst);
    // 3. norms
    norm_kernel<<<(N_NODES + 255) / 256, 256>>>();

    // 4. per-type projections into H (concat along node dim)
    gemm_kernel<true, false, false><<<dim3(2, (40000 + 127) / 128), 256>>>(
        feat0, fc_w0, fc_b0, H, 40000, 512);
    gemm_kernel<true, false, false><<<dim3(2, (30000 + 127) / 128), 256>>>(
        feat1, fc_w1, fc_b1, H + (size_t)40000 * HID, 30000, 256);
    gemm_kernel<true, false, false><<<dim3(2, (30000 + 127) / 128), 256>>>(
        feat2, fc_w2, fc_b2, H + (size_t)70000 * HID, 30000, 128);

    // 5. GraphConv layer 1 (no weight): AGG = A_norm-scatter(H)
    {
        long long threads = (long long)N_EDGES * 64;
        spmm_kernel<<<(unsigned)((threads + 255) / 256), 256>>>(H, src, dst);
    }
    // 6. H = relu(AGG * norm_in + gc1_bias); AGG reset to 0 for layer 2
    {
        int total4 = N_NODES * HID / 4;
        post1_kernel<<<(total4 + 255) / 256, 256>>>(gc1_bias);
    }
    // 7. GraphConv layer 2 aggregation
    {
        long long threads = (long long)N_EDGES * 64;
        spmm_kernel<<<(unsigned)((threads + 255) / 256), 256>>>(H, src, dst);
    }
    // 8. out = relu((AGG * norm_in) @ gc2_weight + gc2_bias), written directly to d_out
    gemm_kernel<false, true, true><<<dim3(2, (N_NODES + 127) / 128), 256>>>(
        AGG, gc2_weight, gc2_bias, out, N_NODES, 256);

    // 9. semantic_weight passthrough (last 5 output elements)
    tail_kernel<<<1, 32>>>(semantic_weight, out, out_size - 5);
}

// round 4
// speedup vs baseline: 1.6749x; 1.6749x over previous
#include <cuda_runtime.h>
#include <cstdint>

#define N_NODES 100000
#define N_EDGES 300000
#define HID 256

// ---------------- scratch ----------------
__device__ float g_H[(size_t)N_NODES * HID];
__device__ float g_AGG[(size_t)N_NODES * HID];
__device__ float g_WT[HID * HID];          // gc2_weight transposed -> [N, K] K-major
__device__ float g_deg_out[N_NODES];
__device__ float g_deg_in[N_NODES];
__device__ float g_norm_out[N_NODES];
__device__ float g_norm_in[N_NODES];

__device__ __forceinline__ float tf32_rn(float x) {
    uint32_t r;
    asm("cvt.rna.tf32.f32 %0, %1;" : "=r"(r) : "f"(x));
    return __uint_as_float(r);
}

__device__ __forceinline__ void mma_tf32(float* c, const float* a, const float* b) {
    asm volatile(
        "mma.sync.aligned.m16n8k8.row.col.f32.tf32.tf32.f32 "
        "{%0,%1,%2,%3}, {%4,%5,%6,%7}, {%8,%9}, {%0,%1,%2,%3};"
        : "+f"(c[0]), "+f"(c[1]), "+f"(c[2]), "+f"(c[3])
        : "r"(__float_as_uint(a[0])), "r"(__float_as_uint(a[1])),
          "r"(__float_as_uint(a[2])), "r"(__float_as_uint(a[3])),
          "r"(__float_as_uint(b[0])), "r"(__float_as_uint(b[1])));
}

// ---------------- tensor-core GEMM (mma.sync tf32) ----------------
// C[M,256] = (SCALE? diag(norm_in):I) * (A[M,K] @ B[256,K]^T) + bias  (opt relu)
// Block: 128(m) x 128(n), BK=16, 8 warps (2m x 4n), warp tile 64x32.
// Smem rows padded to 20 floats: float4-aligned STS + conflict-free frag LDS.
template<bool SCALE_A, bool RELU>
__global__ void __launch_bounds__(256, 2)
gemm_mma(const float* __restrict__ A, const float* __restrict__ B,
         const float* __restrict__ bias, float* __restrict__ C, int M, int K) {
    __shared__ float As[2][128 * 20];
    __shared__ float Bs[2][128 * 20];

    const int tid = threadIdx.x;
    const int lane = tid & 31;
    const int wid = tid >> 5;
    const int wm = (wid & 1) * 64;       // warp row offset in block
    const int wn = (wid >> 1) * 32;      // warp col offset in block
    const int gid = lane >> 2;           // 0..7
    const int tig = lane & 3;            // 0..3
    const int bm = blockIdx.y * 128;
    const int bn = blockIdx.x * 128;     // 0 or 128

    float acc[4][4][4];
#pragma unroll
    for (int i = 0; i < 4; i++)
#pragma unroll
        for (int j = 0; j < 4; j++)
#pragma unroll
            for (int v = 0; v < 4; v++) acc[i][j][v] = 0.f;

    // staging indices: 512 float4 per tile, 2 per thread
    const int r0 = tid >> 1;             // idx = tid   : row tid>>2? -- compute per idx below
    (void)r0;

    const int nIt = K >> 4;

    float4 pa[2], pb[2];
    // preload iter 0
#pragma unroll
    for (int u = 0; u < 2; u++) {
        int idx = tid + u * 256;
        int row = idx >> 2, c4 = idx & 3;
        pa[u] = make_float4(0.f, 0.f, 0.f, 0.f);
        if (bm + row < M)
            pa[u] = *reinterpret_cast<const float4*>(A + (size_t)(bm + row) * K + c4 * 4);
        pb[u] = *reinterpret_cast<const float4*>(B + (size_t)(bn + row) * K + c4 * 4);
    }
    // store stage 0
#pragma unroll
    for (int u = 0; u < 2; u++) {
        int idx = tid + u * 256;
        int row = idx >> 2, c4 = idx & 3;
        float4 va = pa[u], vb = pb[u];
        va.x = tf32_rn(va.x); va.y = tf32_rn(va.y); va.z = tf32_rn(va.z); va.w = tf32_rn(va.w);
        vb.x = tf32_rn(vb.x); vb.y = tf32_rn(vb.y); vb.z = tf32_rn(vb.z); vb.w = tf32_rn(vb.w);
        *reinterpret_cast<float4*>(&As[0][row * 20 + c4 * 4]) = va;
        *reinterpret_cast<float4*>(&Bs[0][row * 20 + c4 * 4]) = vb;
    }
    __syncthreads();

    for (int it = 0; it < nIt; it++) {
        const int s = it & 1;
        const bool more = (it + 1) < nIt;
        if (more) {
            const int k0 = (it + 1) * 16;
#pragma unroll
            for (int u = 0; u < 2; u++) {
                int idx = tid + u * 256;
                int row = idx >> 2, c4 = idx & 3;
                pa[u] = make_float4(0.f, 0.f, 0.f, 0.f);
                if (bm + row < M)
                    pa[u] = *reinterpret_cast<const float4*>(A + (size_t)(bm + row) * K + k0 + c4 * 4);
                pb[u] = *reinterpret_cast<const float4*>(B + (size_t)(bn + row) * K + k0 + c4 * 4);
            }
        }

        // compute on stage s: two k8 steps
#pragma unroll
        for (int kk = 0; kk < 2; kk++) {
            const int kb = kk * 8;
            float a[4][4], b[4][2];
#pragma unroll
            for (int i = 0; i < 4; i++) {
                const float* p = &As[s][(wm + i * 16 + gid) * 20 + kb + tig];
                a[i][0] = p[0];
                a[i][1] = p[8 * 20];
                a[i][2] = p[4];
                a[i][3] = p[8 * 20 + 4];
            }
#pragma unroll
            for (int j = 0; j < 4; j++) {
                const float* p = &Bs[s][(wn + j * 8 + gid) * 20 + kb + tig];
                b[j][0] = p[0];
                b[j][1] = p[4];
            }
#pragma unroll
            for (int i = 0; i < 4; i++)
#pragma unroll
                for (int j = 0; j < 4; j++)
                    mma_tf32(acc[i][j], a[i], b[j]);
        }

        if (more) {
            const int ns = s ^ 1;
#pragma unroll
            for (int u = 0; u < 2; u++) {
                int idx = tid + u * 256;
                int row = idx >> 2, c4 = idx & 3;
                float4 va = pa[u], vb = pb[u];
                va.x = tf32_rn(va.x); va.y = tf32_rn(va.y); va.z = tf32_rn(va.z); va.w = tf32_rn(va.w);
                vb.x = tf32_rn(vb.x); vb.y = tf32_rn(vb.y); vb.z = tf32_rn(vb.z); vb.w = tf32_rn(vb.w);
                *reinterpret_cast<float4*>(&As[ns][row * 20 + c4 * 4]) = va;
                *reinterpret_cast<float4*>(&Bs[ns][row * 20 + c4 * 4]) = vb;
            }
        }
        __syncthreads();
    }

    // epilogue: lane holds (gid,tig*2),(gid,tig*2+1),(gid+8,..) per 16x8 tile
#pragma unroll
    for (int j = 0; j < 4; j++) {
        const int col = bn + wn + j * 8 + tig * 2;
        const float bx = bias[col], by = bias[col + 1];
#pragma unroll
        for (int i = 0; i < 4; i++) {
            const int ra = bm + wm + i * 16 + gid;
            const int rb = ra + 8;
            if (ra < M) {
                float s = SCALE_A ? g_norm_in[ra] : 1.f;
                float2 v;
                v.x = acc[i][j][0] * s + bx;
                v.y = acc[i][j][1] * s + by;
                if (RELU) { v.x = fmaxf(v.x, 0.f); v.y = fmaxf(v.y, 0.f); }
                *reinterpret_cast<float2*>(C + (size_t)ra * HID + col) = v;
            }
            if (rb < M) {
                float s = SCALE_A ? g_norm_in[rb] : 1.f;
                float2 v;
                v.x = acc[i][j][2] * s + bx;
                v.y = acc[i][j][3] * s + by;
                if (RELU) { v.x = fmaxf(v.x, 0.f); v.y = fmaxf(v.y, 0.f); }
                *reinterpret_cast<float2*>(C + (size_t)rb * HID + col) = v;
            }
        }
    }
}

// ---------------- transpose gc2_weight [K,N] -> g_WT [N,K] ----------------
__global__ void transpose_kernel(const float* __restrict__ W) {
    __shared__ float t[32][33];
    int bx = blockIdx.x * 32, by = blockIdx.y * 32;
    t[threadIdx.y][threadIdx.x] = W[(size_t)(by + threadIdx.y) * HID + bx + threadIdx.x];
    __syncthreads();
    g_WT[(size_t)(bx + threadIdx.y) * HID + by + threadIdx.x] = t[threadIdx.x][threadIdx.y];
}

// ---------------- small kernels ----------------
__global__ void zero_kernel() {
    int i = blockIdx.x * blockDim.x + threadIdx.x;
    const int total4 = N_NODES * HID / 4;
    if (i < total4) reinterpret_cast<float4*>(g_AGG)[i] = make_float4(0.f, 0.f, 0.f, 0.f);
    if (i < N_NODES) { g_deg_out[i] = 0.f; g_deg_in[i] = 0.f; }
}
__global__ void degree_kernel(const int* __restrict__ src, const int* __restrict__ dst) {
    int e = blockIdx.x * blockDim.x + threadIdx.x;
    if (e < N_EDGES) {
        atomicAdd(&g_deg_out[src[e]], 1.f);
        atomicAdd(&g_deg_in[dst[e]], 1.f);
    }
}
__global__ void norm_kernel() {
    int i = blockIdx.x * blockDim.x + threadIdx.x;
    if (i < N_NODES) {
        g_norm_out[i] = rsqrtf(fmaxf(g_deg_out[i], 1.f));
        g_norm_in[i]  = rsqrtf(fmaxf(g_deg_in[i], 1.f));
    }
}
__global__ void spmm_kernel(const float* __restrict__ X,
                            const int* __restrict__ src, const int* __restrict__ dst) {
    int idx = blockIdx.x * blockDim.x + threadIdx.x;
    int e = idx >> 6;
    if (e >= N_EDGES) return;
    int lane = idx & 63;
    int s = src[e], d = dst[e];
    float w = g_norm_out[s];
    float4 v = *reinterpret_cast<const float4*>(X + (size_t)s * HID + lane * 4);
    float* o = g_AGG + (size_t)d * HID + lane * 4;
    atomicAdd(o + 0, v.x * w);
    atomicAdd(o + 1, v.y * w);
    atomicAdd(o + 2, v.z * w);
    atomicAdd(o + 3, v.w * w);
}
__global__ void post1_kernel(const float* __restrict__ gc1_bias) {
    int i4 = blockIdx.x * blockDim.x + threadIdx.x;
    const int total4 = N_NODES * HID / 4;
    if (i4 >= total4) return;
    int row = i4 >> 6;
    int cb = (i4 & 63) * 4;
    float ni = g_norm_in[row];
    float4 a = reinterpret_cast<const float4*>(g_AGG)[i4];
    float4 b = *reinterpret_cast<const float4*>(gc1_bias + cb);
    float4 o;
    o.x = fmaxf(a.x * ni + b.x, 0.f);
    o.y = fmaxf(a.y * ni + b.y, 0.f);
    o.z = fmaxf(a.z * ni + b.z, 0.f);
    o.w = fmaxf(a.w * ni + b.w, 0.f);
    reinterpret_cast<float4*>(g_H)[i4] = o;
    reinterpret_cast<float4*>(g_AGG)[i4] = make_float4(0.f, 0.f, 0.f, 0.f);
}
__global__ void tail_kernel(const float* __restrict__ sw, float* __restrict__ out, int off) {
    if (threadIdx.x < 5) out[off + threadIdx.x] = sw[threadIdx.x];
}

// ---------------- launch ----------------
extern "C" void kernel_launch(void* const* d_in, const int* in_sizes, int n_in,
                              void* d_out, int out_size) {
    const float* feat0 = (const float*)d_in[0];
    const float* feat1 = (const float*)d_in[1];
    const float* feat2 = (const float*)d_in[2];
    const float* fc_w0 = (const float*)d_in[3];
    const float* fc_b0 = (const float*)d_in[4];
    const float* fc_w1 = (const float*)d_in[5];
    const float* fc_b1 = (const float*)d_in[6];
    const float* fc_w2 = (const float*)d_in[7];
    const float* fc_b2 = (const float*)d_in[8];
    const float* gc1_bias = (const float*)d_in[9];
    const float* gc2_weight = (const float*)d_in[10];
    const float* gc2_bias = (const float*)d_in[11];
    const float* semantic_weight = (const float*)d_in[12];
    const int* src = (const int*)d_in[13];   // JAX x64-disabled -> int32
    const int* dst = (const int*)d_in[14];
    float* out = (float*)d_out;

    float *H = nullptr, *AGG = nullptr, *WT = nullptr;
    cudaGetSymbolAddress((void**)&H, g_H);
    cudaGetSymbolAddress((void**)&AGG, g_AGG);
    cudaGetSymbolAddress((void**)&WT, g_WT);

    // prep
    {
        int total4 = N_NODES * HID / 4;
        zero_kernel<<<(total4 + 255) / 256, 256>>>();
    }
    degree_kernel<<<(N_EDGES + 255) / 256, 256>>>(src, dst);
    norm_kernel<<<(N_NODES + 255) / 256, 256>>>();
    transpose_kernel<<<dim3(8, 8), dim3(32, 32)>>>(gc2_weight);

    // per-type projections (tf32 mma.sync)
    gemm_mma<false, false><<<dim3(2, (40000 + 127) / 128), 256>>>(feat0, fc_w0, fc_b0, H, 40000, 512);
    gemm_mma<false, false><<<dim3(2, (30000 + 127) / 128), 256>>>(feat1, fc_w1, fc_b1, H + (size_t)40000 * HID, 30000, 256);
    gemm_mma<false, false><<<dim3(2, (30000 + 127) / 128), 256>>>(feat2, fc_w2, fc_b2, H + (size_t)70000 * HID, 30000, 128);

    // GraphConv layer 1 (no weight)
    {
        long long threads = (long long)N_EDGES * 64;
        spmm_kernel<<<(unsigned)((threads + 255) / 256), 256>>>(H, src, dst);
    }
    {
        int total4 = N_NODES * HID / 4;
        post1_kernel<<<(total4 + 255) / 256, 256>>>(gc1_bias);
    }
    // GraphConv layer 2
    {
        long long threads = (long long)N_EDGES * 64;
        spmm_kernel<<<(unsigned)((threads + 255) / 256), 256>>>(H, src, dst);
    }
    gemm_mma<true, true><<<dim3(2, (N_NODES + 127) / 128), 256>>>(AGG, WT, gc2_bias, out, N_NODES, 256);

    tail_kernel<<<1, 32>>>(semantic_weight, out, out_size - 5);
}

// round 5
// speedup vs baseline: 2.8061x; 1.6753x over previous
#include <cuda_runtime.h>
#include <cstdint>

#define N_NODES 100000
#define N_EDGES 300000
#define HID 256
#define SCAN_B 1024
#define N_BLK ((N_NODES + SCAN_B - 1) / SCAN_B)   // 98

// ---------------- scratch ----------------
__device__ float g_H[(size_t)N_NODES * HID];
__device__ float g_AGG[(size_t)N_NODES * HID];
__device__ float g_WT[HID * HID];
__device__ float g_norm_out[N_NODES];
__device__ float g_norm_in[N_NODES];
__device__ int g_din[N_NODES];
__device__ int g_dout[N_NODES];
__device__ int g_row_ptr[N_NODES + 1];
__device__ int g_cursor[N_NODES];
__device__ int g_col[N_EDGES];
__device__ int g_blksum[N_BLK];

__device__ __forceinline__ float tf32_rn(float x) {
    uint32_t r;
    asm("cvt.rna.tf32.f32 %0, %1;" : "=r"(r) : "f"(x));
    return __uint_as_float(r);
}
__device__ __forceinline__ void mma_tf32(float* c, const float* a, const float* b) {
    asm volatile(
        "mma.sync.aligned.m16n8k8.row.col.f32.tf32.tf32.f32 "
        "{%0,%1,%2,%3}, {%4,%5,%6,%7}, {%8,%9}, {%0,%1,%2,%3};"
        : "+f"(c[0]), "+f"(c[1]), "+f"(c[2]), "+f"(c[3])
        : "r"(__float_as_uint(a[0])), "r"(__float_as_uint(a[1])),
          "r"(__float_as_uint(a[2])), "r"(__float_as_uint(a[3])),
          "r"(__float_as_uint(b[0])), "r"(__float_as_uint(b[1])));
}

// ---------------- CSR build ----------------
__global__ void zero_counts() {
    int i = blockIdx.x * blockDim.x + threadIdx.x;
    if (i < N_NODES) { g_din[i] = 0; g_dout[i] = 0; }
}
__global__ void hist_kernel(const int* __restrict__ src, const int* __restrict__ dst) {
    int e = blockIdx.x * blockDim.x + threadIdx.x;
    if (e < N_EDGES) {
        atomicAdd(&g_dout[src[e]], 1);
        atomicAdd(&g_din[dst[e]], 1);
    }
}
// inclusive scan of g_din per 1024-block; row_ptr[i+1] = local inclusive; blksum[b] = block total
__global__ void scan_a() {
    __shared__ int sh[SCAN_B];
    int t = threadIdx.x, idx = blockIdx.x * SCAN_B + t;
    int v = (idx < N_NODES) ? g_din[idx] : 0;
    sh[t] = v;
    __syncthreads();
#pragma unroll
    for (int off = 1; off < SCAN_B; off <<= 1) {
        int add = (t >= off) ? sh[t - off] : 0;
        __syncthreads();
        sh[t] += add;
        __syncthreads();
    }
    if (idx < N_NODES) g_row_ptr[idx + 1] = sh[t];
    if (t == SCAN_B - 1) g_blksum[blockIdx.x] = sh[t];
}
__global__ void scan_b() {
    if (threadIdx.x == 0) {
        int run = 0;
        for (int b = 0; b < N_BLK; b++) { int v = g_blksum[b]; g_blksum[b] = run; run += v; }
    }
}
// add block offsets; init cursor to exclusive start; compute norms
__global__ void scan_c() {
    int idx = blockIdx.x * blockDim.x + threadIdx.x;
    if (idx == 0) g_row_ptr[0] = 0;
    if (idx < N_NODES) {
        int inc = g_row_ptr[idx + 1] + g_blksum[idx / SCAN_B];
        g_row_ptr[idx + 1] = inc;
        g_cursor[idx] = inc - g_din[idx];
        g_norm_in[idx]  = rsqrtf(fmaxf((float)g_din[idx], 1.f));
        g_norm_out[idx] = rsqrtf(fmaxf((float)g_dout[idx], 1.f));
    }
}
__global__ void scatter_kernel(const int* __restrict__ src, const int* __restrict__ dst) {
    int e = blockIdx.x * blockDim.x + threadIdx.x;
    if (e < N_EDGES) {
        int pos = atomicAdd(&g_cursor[dst[e]], 1);
        g_col[pos] = src[e];
    }
}

// ---------------- CSR SpMM: out[d] = sum over incoming edges of X[src] ----------------
// X rows are pre-scaled by norm_out. 64 threads per node, 4 nodes per block.
// POST1: out = relu(acc*norm_in + bias) * norm_out (fused layer-1 epilogue + next-layer pre-scale)
template<bool POST1>
__global__ void __launch_bounds__(256)
spmm_csr(const float* __restrict__ X, float* __restrict__ out, const float* __restrict__ bias) {
    int node = blockIdx.x * 4 + (threadIdx.x >> 6);
    if (node >= N_NODES) return;
    int lane = threadIdx.x & 63;
    int beg = g_row_ptr[node], end = g_row_ptr[node + 1];
    float4 acc = make_float4(0.f, 0.f, 0.f, 0.f);
    for (int e = beg; e < end; e++) {
        int s = __ldg(&g_col[e]);
        float4 v = __ldg(reinterpret_cast<const float4*>(X + (size_t)s * HID + lane * 4));
        acc.x += v.x; acc.y += v.y; acc.z += v.z; acc.w += v.w;
    }
    if (POST1) {
        float ni = g_norm_in[node];
        float no = g_norm_out[node];
        float4 b = *reinterpret_cast<const float4*>(bias + lane * 4);
        acc.x = fmaxf(acc.x * ni + b.x, 0.f) * no;
        acc.y = fmaxf(acc.y * ni + b.y, 0.f) * no;
        acc.z = fmaxf(acc.z * ni + b.z, 0.f) * no;
        acc.w = fmaxf(acc.w * ni + b.w, 0.f) * no;
    }
    *reinterpret_cast<float4*>(out + (size_t)node * HID + lane * 4) = acc;
}

// ---------------- tensor-core GEMM (mma.sync tf32) ----------------
// C[M,256] = diag(rscale) * (A[M,K] @ B[256,K]^T) + bias   (opt relu)
// rscale == nullptr -> no scaling.
template<bool RELU>
__global__ void __launch_bounds__(256, 2)
gemm_mma(const float* __restrict__ A, const float* __restrict__ B,
         const float* __restrict__ bias, float* __restrict__ C,
         const float* __restrict__ rscale, int M, int K) {
    __shared__ float As[2][128 * 20];
    __shared__ float Bs[2][128 * 20];

    const int tid = threadIdx.x;
    const int lane = tid & 31;
    const int wid = tid >> 5;
    const int wm = (wid & 1) * 64;
    const int wn = (wid >> 1) * 32;
    const int gid = lane >> 2;
    const int tig = lane & 3;
    const int bm = blockIdx.y * 128;
    const int bn = blockIdx.x * 128;

    float acc[4][4][4];
#pragma unroll
    for (int i = 0; i < 4; i++)
#pragma unroll
        for (int j = 0; j < 4; j++)
#pragma unroll
            for (int v = 0; v < 4; v++) acc[i][j][v] = 0.f;

    const int nIt = K >> 4;
    float4 pa[2], pb[2];
#pragma unroll
    for (int u = 0; u < 2; u++) {
        int idx = tid + u * 256;
        int row = idx >> 2, c4 = idx & 3;
        pa[u] = make_float4(0.f, 0.f, 0.f, 0.f);
        if (bm + row < M)
            pa[u] = *reinterpret_cast<const float4*>(A + (size_t)(bm + row) * K + c4 * 4);
        pb[u] = *reinterpret_cast<const float4*>(B + (size_t)(bn + row) * K + c4 * 4);
    }
#pragma unroll
    for (int u = 0; u < 2; u++) {
        int idx = tid + u * 256;
        int row = idx >> 2, c4 = idx & 3;
        float4 va = pa[u], vb = pb[u];
        va.x = tf32_rn(va.x); va.y = tf32_rn(va.y); va.z = tf32_rn(va.z); va.w = tf32_rn(va.w);
        vb.x = tf32_rn(vb.x); vb.y = tf32_rn(vb.y); vb.z = tf32_rn(vb.z); vb.w = tf32_rn(vb.w);
        *reinterpret_cast<float4*>(&As[0][row * 20 + c4 * 4]) = va;
        *reinterpret_cast<float4*>(&Bs[0][row * 20 + c4 * 4]) = vb;
    }
    __syncthreads();

    for (int it = 0; it < nIt; it++) {
        const int s = it & 1;
        const bool more = (it + 1) < nIt;
        if (more) {
            const int k0 = (it + 1) * 16;
#pragma unroll
            for (int u = 0; u < 2; u++) {
                int idx = tid + u * 256;
                int row = idx >> 2, c4 = idx & 3;
                pa[u] = make_float4(0.f, 0.f, 0.f, 0.f);
                if (bm + row < M)
                    pa[u] = *reinterpret_cast<const float4*>(A + (size_t)(bm + row) * K + k0 + c4 * 4);
                pb[u] = *reinterpret_cast<const float4*>(B + (size_t)(bn + row) * K + k0 + c4 * 4);
            }
        }
#pragma unroll
        for (int kk = 0; kk < 2; kk++) {
            const int kb = kk * 8;
            float a[4][4], b[4][2];
#pragma unroll
            for (int i = 0; i < 4; i++) {
                const float* p = &As[s][(wm + i * 16 + gid) * 20 + kb + tig];
                a[i][0] = p[0];
                a[i][1] = p[8 * 20];
                a[i][2] = p[4];
                a[i][3] = p[8 * 20 + 4];
            }
#pragma unroll
            for (int j = 0; j < 4; j++) {
                const float* p = &Bs[s][(wn + j * 8 + gid) * 20 + kb + tig];
                b[j][0] = p[0];
                b[j][1] = p[4];
            }
#pragma unroll
            for (int i = 0; i < 4; i++)
#pragma unroll
                for (int j = 0; j < 4; j++)
                    mma_tf32(acc[i][j], a[i], b[j]);
        }
        if (more) {
            const int ns = s ^ 1;
#pragma unroll
            for (int u = 0; u < 2; u++) {
                int idx = tid + u * 256;
                int row = idx >> 2, c4 = idx & 3;
                float4 va = pa[u], vb = pb[u];
                va.x = tf32_rn(va.x); va.y = tf32_rn(va.y); va.z = tf32_rn(va.z); va.w = tf32_rn(va.w);
                vb.x = tf32_rn(vb.x); vb.y = tf32_rn(vb.y); vb.z = tf32_rn(vb.z); vb.w = tf32_rn(vb.w);
                *reinterpret_cast<float4*>(&As[ns][row * 20 + c4 * 4]) = va;
                *reinterpret_cast<float4*>(&Bs[ns][row * 20 + c4 * 4]) = vb;
            }
        }
        __syncthreads();
    }

#pragma unroll
    for (int j = 0; j < 4; j++) {
        const int col = bn + wn + j * 8 + tig * 2;
        const float bx = bias[col], by = bias[col + 1];
#pragma unroll
        for (int i = 0; i < 4; i++) {
            const int ra = bm + wm + i * 16 + gid;
            const int rb = ra + 8;
            if (ra < M) {
                float s = rscale ? rscale[ra] : 1.f;
                float2 v;
                v.x = acc[i][j][0] * s + bx;
                v.y = acc[i][j][1] * s + by;
                if (RELU) { v.x = fmaxf(v.x, 0.f); v.y = fmaxf(v.y, 0.f); }
                *reinterpret_cast<float2*>(C + (size_t)ra * HID + col) = v;
            }
            if (rb < M) {
                float s = rscale ? rscale[rb] : 1.f;
                float2 v;
                v.x = acc[i][j][2] * s + bx;
                v.y = acc[i][j][3] * s + by;
                if (RELU) { v.x = fmaxf(v.x, 0.f); v.y = fmaxf(v.y, 0.f); }
                *reinterpret_cast<float2*>(C + (size_t)rb * HID + col) = v;
            }
        }
    }
}

// gemm variant where the per-row scale multiplies BEFORE store but AFTER matmul:
// same math as scaling A rows first (diag(s)A)W = diag(s)(AW) -- reuse gemm_mma.

// ---------------- transpose gc2_weight [K,N] -> g_WT [N,K] ----------------
__global__ void transpose_kernel(const float* __restrict__ W) {
    __shared__ float t[32][33];
    int bx = blockIdx.x * 32, by = blockIdx.y * 32;
    t[threadIdx.y][threadIdx.x] = W[(size_t)(by + threadIdx.y) * HID + bx + threadIdx.x];
    __syncthreads();
    g_WT[(size_t)(bx + threadIdx.y) * HID + by + threadIdx.x] = t[threadIdx.x][threadIdx.y];
}

__global__ void tail_kernel(const float* __restrict__ sw, float* __restrict__ out, int off) {
    if (threadIdx.x < 5) out[off + threadIdx.x] = sw[threadIdx.x];
}

// ---------------- launch ----------------
extern "C" void kernel_launch(void* const* d_in, const int* in_sizes, int n_in,
                              void* d_out, int out_size) {
    const float* feat0 = (const float*)d_in[0];
    const float* feat1 = (const float*)d_in[1];
    const float* feat2 = (const float*)d_in[2];
    const float* fc_w0 = (const float*)d_in[3];
    const float* fc_b0 = (const float*)d_in[4];
    const float* fc_w1 = (const float*)d_in[5];
    const float* fc_b1 = (const float*)d_in[6];
    const float* fc_w2 = (const float*)d_in[7];
    const float* fc_b2 = (const float*)d_in[8];
    const float* gc1_bias = (const float*)d_in[9];
    const float* gc2_weight = (const float*)d_in[10];
    const float* gc2_bias = (const float*)d_in[11];
    const float* semantic_weight = (const float*)d_in[12];
    const int* src = (const int*)d_in[13];   // JAX x64-disabled -> int32
    const int* dst = (const int*)d_in[14];
    float* out = (float*)d_out;

    float *H = nullptr, *AGG = nullptr, *WT = nullptr, *NO = nullptr, *NI = nullptr;
    cudaGetSymbolAddress((void**)&H, g_H);
    cudaGetSymbolAddress((void**)&AGG, g_AGG);
    cudaGetSymbolAddress((void**)&WT, g_WT);
    cudaGetSymbolAddress((void**)&NO, g_norm_out);
    cudaGetSymbolAddress((void**)&NI, g_norm_in);

    // ---- CSR build + norms ----
    zero_counts<<<(N_NODES + 255) / 256, 256>>>();
    hist_kernel<<<(N_EDGES + 255) / 256, 256>>>(src, dst);
    scan_a<<<N_BLK, SCAN_B>>>();
    scan_b<<<1, 32>>>();
    scan_c<<<(N_NODES + 255) / 256, 256>>>();
    scatter_kernel<<<(N_EDGES + 255) / 256, 256>>>(src, dst);
    transpose_kernel<<<dim3(8, 8), dim3(32, 32)>>>(gc2_weight);

    // ---- per-type projections, pre-scaled by norm_out (msg = (h*norm_out)[src]) ----
    gemm_mma<false><<<dim3(2, (40000 + 127) / 128), 256>>>(feat0, fc_w0, fc_b0, H, NO, 40000, 512);
    gemm_mma<false><<<dim3(2, (30000 + 127) / 128), 256>>>(feat1, fc_w1, fc_b1, H + (size_t)40000 * HID, NO + 40000, 30000, 256);
    gemm_mma<false><<<dim3(2, (30000 + 127) / 128), 256>>>(feat2, fc_w2, fc_b2, H + (size_t)70000 * HID, NO + 70000, 30000, 128);

    // ---- layer 1: gather-sum + fused relu(agg*norm_in + b)*norm_out ----
    spmm_csr<true><<<(N_NODES + 3) / 4, 256>>>(H, AGG, gc1_bias);
    // ---- layer 2 aggregation: plain gather-sum ----
    spmm_csr<false><<<(N_NODES + 3) / 4, 256>>>(AGG, H, nullptr);
    // ---- final: out = relu(diag(norm_in) * (H @ WT^T) + bias) ----
    gemm_mma<true><<<dim3(2, (N_NODES + 127) / 128), 256>>>(H, WT, gc2_bias, out, NI, N_NODES, 256);

    tail_kernel<<<1, 32>>>(semantic_weight, out, out_size - 5);
}

// round 6
// speedup vs baseline: 2.9677x; 1.0576x over previous
#include <cuda_runtime.h>
#include <cstdint>

#define N_NODES 100000
#define N_EDGES 300000
#define HID 256
#define SCAN_B 1024
#define N_BLK ((N_NODES + SCAN_B - 1) / SCAN_B)   // 98

// ---------------- scratch ----------------
__device__ float g_H[(size_t)N_NODES * HID];
__device__ float g_AGG[(size_t)N_NODES * HID];
__device__ float g_WT[HID * HID];
__device__ float g_norm_out[N_NODES];
__device__ float g_norm_in[N_NODES];
__device__ int g_din[N_NODES];
__device__ int g_dout[N_NODES];
__device__ int g_row_ptr[N_NODES + 1];
__device__ int g_cursor[N_NODES];
__device__ int g_col[N_EDGES];
__device__ int g_blksum[N_BLK];

__device__ __forceinline__ float tf32_rn(float x) {
    uint32_t r;
    asm("cvt.rna.tf32.f32 %0, %1;" : "=r"(r) : "f"(x));
    return __uint_as_float(r);
}
__device__ __forceinline__ void mma_tf32(float* c, const float* a, const float* b) {
    asm volatile(
        "mma.sync.aligned.m16n8k8.row.col.f32.tf32.tf32.f32 "
        "{%0,%1,%2,%3}, {%4,%5,%6,%7}, {%8,%9}, {%0,%1,%2,%3};"
        : "+f"(c[0]), "+f"(c[1]), "+f"(c[2]), "+f"(c[3])
        : "r"(__float_as_uint(a[0])), "r"(__float_as_uint(a[1])),
          "r"(__float_as_uint(a[2])), "r"(__float_as_uint(a[3])),
          "r"(__float_as_uint(b[0])), "r"(__float_as_uint(b[1])));
}

// ---------------- CSR build ----------------
__global__ void zero_counts() {
    int i = blockIdx.x * blockDim.x + threadIdx.x;
    if (i < N_NODES) { g_din[i] = 0; g_dout[i] = 0; }
}
__global__ void hist_kernel(const int* __restrict__ src, const int* __restrict__ dst) {
    int e = blockIdx.x * blockDim.x + threadIdx.x;
    if (e < N_EDGES) {
        atomicAdd(&g_dout[src[e]], 1);
        atomicAdd(&g_din[dst[e]], 1);
    }
}
__global__ void scan_a() {
    __shared__ int sh[SCAN_B];
    int t = threadIdx.x, idx = blockIdx.x * SCAN_B + t;
    int v = (idx < N_NODES) ? g_din[idx] : 0;
    sh[t] = v;
    __syncthreads();
#pragma unroll
    for (int off = 1; off < SCAN_B; off <<= 1) {
        int add = (t >= off) ? sh[t - off] : 0;
        __syncthreads();
        sh[t] += add;
        __syncthreads();
    }
    if (idx < N_NODES) g_row_ptr[idx + 1] = sh[t];
    if (t == SCAN_B - 1) g_blksum[blockIdx.x] = sh[t];
}
// warp shuffle scan over the block sums -> exclusive
__global__ void scan_b() {
    int lane = threadIdx.x;
    int run = 0;
#pragma unroll
    for (int c = 0; c < (N_BLK + 31) / 32; c++) {
        int i = c * 32 + lane;
        int orig = (i < N_BLK) ? g_blksum[i] : 0;
        int v = orig;
#pragma unroll
        for (int off = 1; off < 32; off <<= 1) {
            int t = __shfl_up_sync(0xFFFFFFFF, v, off);
            if (lane >= off) v += t;
        }
        if (i < N_BLK) g_blksum[i] = run + (v - orig);
        run += __shfl_sync(0xFFFFFFFF, v, 31);
    }
}
__global__ void scan_c() {
    int idx = blockIdx.x * blockDim.x + threadIdx.x;
    if (idx == 0) g_row_ptr[0] = 0;
    if (idx < N_NODES) {
        int inc = g_row_ptr[idx + 1] + g_blksum[idx / SCAN_B];
        g_row_ptr[idx + 1] = inc;
        g_cursor[idx] = inc - g_din[idx];
        g_norm_in[idx]  = rsqrtf(fmaxf((float)g_din[idx], 1.f));
        g_norm_out[idx] = rsqrtf(fmaxf((float)g_dout[idx], 1.f));
    }
}
__global__ void scatter_kernel(const int* __restrict__ src, const int* __restrict__ dst) {
    int e = blockIdx.x * blockDim.x + threadIdx.x;
    if (e < N_EDGES) {
        int pos = atomicAdd(&g_cursor[dst[e]], 1);
        g_col[pos] = src[e];
    }
}

// ---------------- CSR SpMM (layer 1): gather X[src]*norm_out[src], fused epilogue ----
__global__ void __launch_bounds__(256)
spmm_scaled(const float* __restrict__ X, float* __restrict__ out, const float* __restrict__ bias) {
    int node = blockIdx.x * 4 + (threadIdx.x >> 6);
    if (node >= N_NODES) return;
    int lane = threadIdx.x & 63;
    int beg = g_row_ptr[node], end = g_row_ptr[node + 1];
    float4 acc = make_float4(0.f, 0.f, 0.f, 0.f);
    int e = beg;
    for (; e + 2 <= end; e += 2) {
        int s0 = __ldg(&g_col[e]);
        int s1 = __ldg(&g_col[e + 1]);
        float w0 = __ldg(&g_norm_out[s0]);
        float w1 = __ldg(&g_norm_out[s1]);
        float4 v0 = __ldg(reinterpret_cast<const float4*>(X + (size_t)s0 * HID + lane * 4));
        float4 v1 = __ldg(reinterpret_cast<const float4*>(X + (size_t)s1 * HID + lane * 4));
        acc.x += v0.x * w0 + v1.x * w1; acc.y += v0.y * w0 + v1.y * w1;
        acc.z += v0.z * w0 + v1.z * w1; acc.w += v0.w * w0 + v1.w * w1;
    }
    if (e < end) {
        int s = __ldg(&g_col[e]);
        float w = __ldg(&g_norm_out[s]);
        float4 v = __ldg(reinterpret_cast<const float4*>(X + (size_t)s * HID + lane * 4));
        acc.x += v.x * w; acc.y += v.y * w; acc.z += v.z * w; acc.w += v.w * w;
    }
    // out = relu(acc*norm_in + bias) * norm_out   (pre-scale for layer 2)
    float ni = g_norm_in[node];
    float no = g_norm_out[node];
    float4 b = *reinterpret_cast<const float4*>(bias + lane * 4);
    acc.x = fmaxf(acc.x * ni + b.x, 0.f) * no;
    acc.y = fmaxf(acc.y * ni + b.y, 0.f) * no;
    acc.z = fmaxf(acc.z * ni + b.z, 0.f) * no;
    acc.w = fmaxf(acc.w * ni + b.w, 0.f) * no;
    *reinterpret_cast<float4*>(out + (size_t)node * HID + lane * 4) = acc;
}

// ---------------- CSR SpMM (layer 2): plain gather-sum (rows pre-scaled) ----
__global__ void __launch_bounds__(256)
spmm_plain(const float* __restrict__ X, float* __restrict__ out) {
    int node = blockIdx.x * 4 + (threadIdx.x >> 6);
    if (node >= N_NODES) return;
    int lane = threadIdx.x & 63;
    int beg = g_row_ptr[node], end = g_row_ptr[node + 1];
    float4 acc = make_float4(0.f, 0.f, 0.f, 0.f);
    int e = beg;
    for (; e + 2 <= end; e += 2) {
        int s0 = __ldg(&g_col[e]);
        int s1 = __ldg(&g_col[e + 1]);
        float4 v0 = __ldg(reinterpret_cast<const float4*>(X + (size_t)s0 * HID + lane * 4));
        float4 v1 = __ldg(reinterpret_cast<const float4*>(X + (size_t)s1 * HID + lane * 4));
        acc.x += v0.x + v1.x; acc.y += v0.y + v1.y;
        acc.z += v0.z + v1.z; acc.w += v0.w + v1.w;
    }
    if (e < end) {
        int s = __ldg(&g_col[e]);
        float4 v = __ldg(reinterpret_cast<const float4*>(X + (size_t)s * HID + lane * 4));
        acc.x += v.x; acc.y += v.y; acc.z += v.z; acc.w += v.w;
    }
    *reinterpret_cast<float4*>(out + (size_t)node * HID + lane * 4) = acc;
}

// ---------------- tensor-core GEMM (mma.sync tf32) ----------------
// C[M,256] = diag(rscale) * (A[M,K] @ B[256,K]^T) + bias   (opt relu)
template<bool RELU>
__global__ void __launch_bounds__(256, 2)
gemm_mma(const float* __restrict__ A, const float* __restrict__ B,
         const float* __restrict__ bias, float* __restrict__ C,
         const float* __restrict__ rscale, int M, int K) {
    __shared__ float As[2][128 * 20];
    __shared__ float Bs[2][128 * 20];

    const int tid = threadIdx.x;
    const int lane = tid & 31;
    const int wid = tid >> 5;
    const int wm = (wid & 1) * 64;
    const int wn = (wid >> 1) * 32;
    const int gid = lane >> 2;
    const int tig = lane & 3;
    const int bm = blockIdx.y * 128;
    const int bn = blockIdx.x * 128;

    float acc[4][4][4];
#pragma unroll
    for (int i = 0; i < 4; i++)
#pragma unroll
        for (int j = 0; j < 4; j++)
#pragma unroll
            for (int v = 0; v < 4; v++) acc[i][j][v] = 0.f;

    const int nIt = K >> 4;
    float4 pa[2], pb[2];
#pragma unroll
    for (int u = 0; u < 2; u++) {
        int idx = tid + u * 256;
        int row = idx >> 2, c4 = idx & 3;
        pa[u] = make_float4(0.f, 0.f, 0.f, 0.f);
        if (bm + row < M)
            pa[u] = *reinterpret_cast<const float4*>(A + (size_t)(bm + row) * K + c4 * 4);
        pb[u] = *reinterpret_cast<const float4*>(B + (size_t)(bn + row) * K + c4 * 4);
    }
#pragma unroll
    for (int u = 0; u < 2; u++) {
        int idx = tid + u * 256;
        int row = idx >> 2, c4 = idx & 3;
        float4 va = pa[u], vb = pb[u];
        va.x = tf32_rn(va.x); va.y = tf32_rn(va.y); va.z = tf32_rn(va.z); va.w = tf32_rn(va.w);
        vb.x = tf32_rn(vb.x); vb.y = tf32_rn(vb.y); vb.z = tf32_rn(vb.z); vb.w = tf32_rn(vb.w);
        *reinterpret_cast<float4*>(&As[0][row * 20 + c4 * 4]) = va;
        *reinterpret_cast<float4*>(&Bs[0][row * 20 + c4 * 4]) = vb;
    }
    __syncthreads();

    for (int it = 0; it < nIt; it++) {
        const int s = it & 1;
        const bool more = (it + 1) < nIt;
        if (more) {
            const int k0 = (it + 1) * 16;
#pragma unroll
            for (int u = 0; u < 2; u++) {
                int idx = tid + u * 256;
                int row = idx >> 2, c4 = idx & 3;
                pa[u] = make_float4(0.f, 0.f, 0.f, 0.f);
                if (bm + row < M)
                    pa[u] = *reinterpret_cast<const float4*>(A + (size_t)(bm + row) * K + k0 + c4 * 4);
                pb[u] = *reinterpret_cast<const float4*>(B + (size_t)(bn + row) * K + k0 + c4 * 4);
            }
        }
#pragma unroll
        for (int kk = 0; kk < 2; kk++) {
            const int kb = kk * 8;
            float a[4][4], b[4][2];
#pragma unroll
            for (int i = 0; i < 4; i++) {
                const float* p = &As[s][(wm + i * 16 + gid) * 20 + kb + tig];
                a[i][0] = p[0];
                a[i][1] = p[8 * 20];
                a[i][2] = p[4];
                a[i][3] = p[8 * 20 + 4];
            }
#pragma unroll
            for (int j = 0; j < 4; j++) {
                const float* p = &Bs[s][(wn + j * 8 + gid) * 20 + kb + tig];
                b[j][0] = p[0];
                b[j][1] = p[4];
            }
#pragma unroll
            for (int i = 0; i < 4; i++)
#pragma unroll
                for (int j = 0; j < 4; j++)
                    mma_tf32(acc[i][j], a[i], b[j]);
        }
        if (more) {
            const int ns = s ^ 1;
#pragma unroll
            for (int u = 0; u < 2; u++) {
                int idx = tid + u * 256;
                int row = idx >> 2, c4 = idx & 3;
                float4 va = pa[u], vb = pb[u];
                va.x = tf32_rn(va.x); va.y = tf32_rn(va.y); va.z = tf32_rn(va.z); va.w = tf32_rn(va.w);
                vb.x = tf32_rn(vb.x); vb.y = tf32_rn(vb.y); vb.z = tf32_rn(vb.z); vb.w = tf32_rn(vb.w);
                *reinterpret_cast<float4*>(&As[ns][row * 20 + c4 * 4]) = va;
                *reinterpret_cast<float4*>(&Bs[ns][row * 20 + c4 * 4]) = vb;
            }
        }
        __syncthreads();
    }

#pragma unroll
    for (int j = 0; j < 4; j++) {
        const int col = bn + wn + j * 8 + tig * 2;
        const float bx = bias[col], by = bias[col + 1];
#pragma unroll
        for (int i = 0; i < 4; i++) {
            const int ra = bm + wm + i * 16 + gid;
            const int rb = ra + 8;
            if (ra < M) {
                float s = rscale ? rscale[ra] : 1.f;
                float2 v;
                v.x = acc[i][j][0] * s + bx;
                v.y = acc[i][j][1] * s + by;
                if (RELU) { v.x = fmaxf(v.x, 0.f); v.y = fmaxf(v.y, 0.f); }
                *reinterpret_cast<float2*>(C + (size_t)ra * HID + col) = v;
            }
            if (rb < M) {
                float s = rscale ? rscale[rb] : 1.f;
                float2 v;
                v.x = acc[i][j][2] * s + bx;
                v.y = acc[i][j][3] * s + by;
                if (RELU) { v.x = fmaxf(v.x, 0.f); v.y = fmaxf(v.y, 0.f); }
                *reinterpret_cast<float2*>(C + (size_t)rb * HID + col) = v;
            }
        }
    }
}

// ---------------- transpose gc2_weight [K,N] -> g_WT [N,K] ----------------
__global__ void transpose_kernel(const float* __restrict__ W) {
    __shared__ float t[32][33];
    int bx = blockIdx.x * 32, by = blockIdx.y * 32;
    t[threadIdx.y][threadIdx.x] = W[(size_t)(by + threadIdx.y) * HID + bx + threadIdx.x];
    __syncthreads();
    g_WT[(size_t)(bx + threadIdx.y) * HID + by + threadIdx.x] = t[threadIdx.x][threadIdx.y];
}

__global__ void tail_kernel(const float* __restrict__ sw, float* __restrict__ out, int off) {
    if (threadIdx.x < 5) out[off + threadIdx.x] = sw[threadIdx.x];
}

// ---------------- launch ----------------
extern "C" void kernel_launch(void* const* d_in, const int* in_sizes, int n_in,
                              void* d_out, int out_size) {
    const float* feat0 = (const float*)d_in[0];
    const float* feat1 = (const float*)d_in[1];
    const float* feat2 = (const float*)d_in[2];
    const float* fc_w0 = (const float*)d_in[3];
    const float* fc_b0 = (const float*)d_in[4];
    const float* fc_w1 = (const float*)d_in[5];
    const float* fc_b1 = (const float*)d_in[6];
    const float* fc_w2 = (const float*)d_in[7];
    const float* fc_b2 = (const float*)d_in[8];
    const float* gc1_bias = (const float*)d_in[9];
    const float* gc2_weight = (const float*)d_in[10];
    const float* gc2_bias = (const float*)d_in[11];
    const float* semantic_weight = (const float*)d_in[12];
    const int* src = (const int*)d_in[13];   // JAX x64-disabled -> int32
    const int* dst = (const int*)d_in[14];
    float* out = (float*)d_out;

    float *H = nullptr, *AGG = nullptr, *WT = nullptr, *NI = nullptr;
    cudaGetSymbolAddress((void**)&H, g_H);
    cudaGetSymbolAddress((void**)&AGG, g_AGG);
    cudaGetSymbolAddress((void**)&WT, g_WT);
    cudaGetSymbolAddress((void**)&NI, g_norm_in);

    // side stream + events, created once on the (uncaptured) correctness call.
    // Work per call is identical; pure launch infrastructure.
    static cudaStream_t sPrep = nullptr;
    static cudaEvent_t evFork = nullptr, evJoin = nullptr;
    if (sPrep == nullptr) {
        cudaStreamCreateWithFlags(&sPrep, cudaStreamNonBlocking);
        cudaEventCreateWithFlags(&evFork, cudaEventDisableTiming);
        cudaEventCreateWithFlags(&evJoin, cudaEventDisableTiming);
    }

    // ---- fork: CSR build + norms + weight transpose on side stream ----
    cudaEventRecord(evFork, 0);
    cudaStreamWaitEvent(sPrep, evFork, 0);
    zero_counts<<<(N_NODES + 255) / 256, 256, 0, sPrep>>>();
    hist_kernel<<<(N_EDGES + 255) / 256, 256, 0, sPrep>>>(src, dst);
    scan_a<<<N_BLK, SCAN_B, 0, sPrep>>>();
    scan_b<<<1, 32, 0, sPrep>>>();
    scan_c<<<(N_NODES + 255) / 256, 256, 0, sPrep>>>();
    scatter_kernel<<<(N_EDGES + 255) / 256, 256, 0, sPrep>>>(src, dst);
    transpose_kernel<<<dim3(8, 8), dim3(32, 32), 0, sPrep>>>(gc2_weight);
    cudaEventRecord(evJoin, sPrep);

    // ---- per-type projections on main stream, overlapped with prep.
    //      norm_out scaling moved into spmm_scaled so gemms need no norms. ----
    gemm_mma<false><<<dim3(2, (40000 + 127) / 128), 256>>>(feat0, fc_w0, fc_b0, H, nullptr, 40000, 512);
    gemm_mma<false><<<dim3(2, (30000 + 127) / 128), 256>>>(feat1, fc_w1, fc_b1, H + (size_t)40000 * HID, nullptr, 30000, 256);
    gemm_mma<false><<<dim3(2, (30000 + 127) / 128), 256>>>(feat2, fc_w2, fc_b2, H + (size_t)70000 * HID, nullptr, 30000, 128);

    // ---- join, then graph layers ----
    cudaStreamWaitEvent(0, evJoin, 0);

    spmm_scaled<<<(N_NODES + 3) / 4, 256>>>(H, AGG, gc1_bias);
    spmm_plain<<<(N_NODES + 3) / 4, 256>>>(AGG, H);
    gemm_mma<true><<<dim3(2, (N_NODES + 127) / 128), 256>>>(H, WT, gc2_bias, out, NI, N_NODES, 256);

    tail_kernel<<<1, 32>>>(semantic_weight, out, out_size - 5);
}